// round 3
// baseline (speedup 1.0000x reference)
#include <cuda_runtime.h>
#include <cstdint>
#include <cstddef>

// Problem constants (fixed by setup_inputs)
#define DIMSZ   1024
#define HD      64
#define NHEADS  16
#define BL      4096            // B*L
#define MROWS   2048
#define QT      256             // queries per attention CTA
#define MC      64              // memory rows per chunk
#define NCH     (MROWS / MC)    // 32
// BETA * log2(e): softmax in base 2 (single EX2 per element)
#define SCALE_LOG2 23.083120654223414f

typedef unsigned long long ull;

// ping-pong scratch (no allocations allowed)
__device__ float g_bufA[(size_t)BL * DIMSZ];
__device__ float g_bufB[(size_t)BL * DIMSZ];

// ---------------- packed f32x2 helpers ----------------
__device__ __forceinline__ ull pack2(float lo, float hi) {
    ull r; asm("mov.b64 %0, {%1, %2};" : "=l"(r) : "f"(lo), "f"(hi)); return r;
}
__device__ __forceinline__ void unpack2(ull v, float& lo, float& hi) {
    asm("mov.b64 {%0, %1}, %2;" : "=f"(lo), "=f"(hi) : "l"(v));
}
__device__ __forceinline__ void ffma2(ull& d, ull a, ull b) {
    asm("fma.rn.f32x2 %0, %1, %2, %0;" : "+l"(d) : "l"(a), "l"(b));
}
__device__ __forceinline__ ull mul2(ull a, ull b) {
    ull r; asm("mul.rn.f32x2 %0, %1, %2;" : "=l"(r) : "l"(a), "l"(b)); return r;
}
__device__ __forceinline__ float ex2(float x) {
    float r; asm("ex2.approx.f32 %0, %1;" : "=f"(r) : "f"(x)); return r;
}

// =======================================================================
// Dense linear: C[4096][1024] = A @ W^T + bias   (torch Linear, W=[out,in])
// Tile 128x128, kt=16, 256 thr, 8x8 micro. A stored DUPLICATED in smem so
// the inner loop is pure LDS + ffma2 (no mov.b64). Register double-buffered
// global loads.
// =======================================================================
__global__ void __launch_bounds__(256, 2)
linear_kernel(float* __restrict__ C, const float* __restrict__ A,
              const float* __restrict__ W, const float* __restrict__ bias)
{
    __shared__ float As2[16][264];   // As2[k][2i] = As2[k][2i+1] = A[i][k]
    __shared__ float Bs[16][132];    // Bs[k][j]
    const int tid = threadIdx.x;
    const int tx  = tid & 15;        // j-tile
    const int ty  = tid >> 4;        // i-tile
    const int i0  = blockIdx.y * 128;
    const int j0  = blockIdx.x * 128;

    // accumulators pre-initialized with bias (pairs along j)
    ull acc[8][4];
    {
        const float* bp = bias + j0 + tx * 8;
        float4 b0 = *(const float4*)bp;
        float4 b1 = *(const float4*)(bp + 4);
        ull p0 = pack2(b0.x, b0.y), p1 = pack2(b0.z, b0.w);
        ull p2 = pack2(b1.x, b1.y), p3 = pack2(b1.z, b1.w);
        #pragma unroll
        for (int ii = 0; ii < 8; ii++) {
            acc[ii][0] = p0; acc[ii][1] = p1; acc[ii][2] = p2; acc[ii][3] = p3;
        }
    }

    const int lk = tid & 15;        // k within tile
    const int ib = tid >> 4;        // base row

    const float* Ag = A + (size_t)(i0 + ib) * DIMSZ + lk;
    const float* Wg = W + (size_t)(j0 + ib) * DIMSZ + lk;

    // prefetch kt = 0
    float rA[8], rW[8];
    #pragma unroll
    for (int rep = 0; rep < 8; rep++) {
        rA[rep] = Ag[(size_t)rep * 16 * DIMSZ];
        rW[rep] = Wg[(size_t)rep * 16 * DIMSZ];
    }

    for (int kt = 0; kt < 64; kt++) {
        __syncthreads();
        #pragma unroll
        for (int rep = 0; rep < 8; rep++) {
            *(ull*)&As2[lk][2 * (ib + rep * 16)] = pack2(rA[rep], rA[rep]);
            Bs[lk][ib + rep * 16] = rW[rep];
        }
        // prefetch next k-tile (wraps harmlessly on last iter)
        {
            const int ktn = (kt + 1) & 63;
            const float* Agn = Ag + ktn * 16;
            const float* Wgn = Wg + ktn * 16;
            #pragma unroll
            for (int rep = 0; rep < 8; rep++) {
                rA[rep] = Agn[(size_t)rep * 16 * DIMSZ];
                rW[rep] = Wgn[(size_t)rep * 16 * DIMSZ];
            }
        }
        __syncthreads();
        #pragma unroll
        for (int k = 0; k < 16; k++) {
            const float* ap = &As2[k][16 * ty];          // dup pairs
            ulonglong2 a01 = *(const ulonglong2*)ap;      // ii=0,1
            ulonglong2 a23 = *(const ulonglong2*)(ap + 4);
            ulonglong2 a45 = *(const ulonglong2*)(ap + 8);
            ulonglong2 a67 = *(const ulonglong2*)(ap + 12);
            const float* bp = &Bs[k][tx * 8];
            ulonglong2 w0 = *(const ulonglong2*)bp;       // j pairs 0..3
            ulonglong2 w1 = *(const ulonglong2*)(bp + 4); // j pairs 4..7
            ull ad[8] = {a01.x, a01.y, a23.x, a23.y, a45.x, a45.y, a67.x, a67.y};
            #pragma unroll
            for (int ii = 0; ii < 8; ii++) {
                ffma2(acc[ii][0], ad[ii], w0.x);
                ffma2(acc[ii][1], ad[ii], w0.y);
                ffma2(acc[ii][2], ad[ii], w1.x);
                ffma2(acc[ii][3], ad[ii], w1.y);
            }
        }
    }

    // epilogue
    #pragma unroll
    for (int ii = 0; ii < 8; ii++) {
        float4 o0, o1;
        unpack2(acc[ii][0], o0.x, o0.y);
        unpack2(acc[ii][1], o0.z, o0.w);
        unpack2(acc[ii][2], o1.x, o1.y);
        unpack2(acc[ii][3], o1.z, o1.w);
        float* cp = C + (size_t)(i0 + ty * 8 + ii) * DIMSZ + j0 + tx * 8;
        *(float4*)cp       = o0;
        *(float4*)(cp + 4) = o1;
    }
}

// =======================================================================
// Fused Hopfield retrieval (one iteration):
//   dst[r, h*64+d] = sum_m softmax_m(16 * q . mem[m]) * mem[m, d]
// CTA: 256 query rows x 1 head, 512 threads (16 warps). Flash-style online
// softmax over 32 chunks of 64 memory rows. K stored duplicated (for dup-free
// ffma2); Q natural pairs along q. PV split into two m-groups with private
// partial accumulators (combined at the end).
// =======================================================================
// dynamic smem layout (floats):
#define SM_QTS   0                          // Qts[64][260]  (transposed, scaled)
#define SM_KTD   (64 * 260)                 // Ktsd[64][132] (transposed, DUP along m)
#define SM_VS    (SM_KTD + 64 * 132)        // Vs[64][68]    (straight V chunk)
#define SM_PS    (SM_VS + 64 * 68)          // Ps[256][68]   (P; reused for O-partials)
#define SM_ALPHA (SM_PS + 256 * 68)         // [256]
#define SM_MAXR  (SM_ALPHA + 256)           // [256] running max
#define SM_LSUM  (SM_MAXR + 256)            // [256] running sum
#define SM_FLOATS (SM_LSUM + 256)
#define SM_BYTES  (SM_FLOATS * 4)           // 190464 B

__global__ void __launch_bounds__(512, 1)
hopfield_attn_kernel(float* __restrict__ dst, const float* __restrict__ src,
                     const float* __restrict__ mem)
{
    extern __shared__ float sm[];
    float* Qts    = sm + SM_QTS;
    float* Ktsd   = sm + SM_KTD;
    float* Vs     = sm + SM_VS;
    float* Ps     = sm + SM_PS;
    float* rAlpha = sm + SM_ALPHA;
    float* rMax   = sm + SM_MAXR;
    float* rLsum  = sm + SM_LSUM;

    const int tid = threadIdx.x;
    const int h   = blockIdx.y;
    const int r0  = blockIdx.x * QT;

    // ---- load Q (scaled), transposed Qts[d][i] ----
    {
        const int i = tid & 255, seg = tid >> 8;
        const float* gq = src + (size_t)(r0 + i) * DIMSZ + h * HD + seg * 32;
        #pragma unroll
        for (int j = 0; j < 8; j++) {
            float4 v = *(const float4*)(gq + 4 * j);
            int d = seg * 32 + 4 * j;
            Qts[(d + 0) * 260 + i] = v.x * SCALE_LOG2;
            Qts[(d + 1) * 260 + i] = v.y * SCALE_LOG2;
            Qts[(d + 2) * 260 + i] = v.z * SCALE_LOG2;
            Qts[(d + 3) * 260 + i] = v.w * SCALE_LOG2;
        }
    }
    if (tid < QT) { rMax[tid] = -1e30f; rLsum[tid] = 0.0f; }

    // S-phase coords: 16 m-tiles (4 m each) x 32 q-tiles (8 q each, paired)
    const int mt = tid & 15;
    const int qt = tid >> 4;
    // PV coords: 2 m-groups x (8 d-groups x 32 q-groups); q = qg + 32*qi
    const int g  = tid >> 8;
    const int lg = tid & 255;
    const int dg = lg & 7;
    const int qg = lg >> 3;

    // loader coords + chunk-0 prefetch
    const int lm = tid & 63, lseg = tid >> 6;   // lseg 0..7
    float4 pf0, pf1;
    {
        const float* gk = mem + (size_t)lm * HD + lseg * 8;
        pf0 = *(const float4*)gk;
        pf1 = *(const float4*)(gk + 4);
    }

    ull Opk[8][4];
    #pragma unroll
    for (int qi = 0; qi < 8; qi++)
        #pragma unroll
        for (int dp = 0; dp < 4; dp++) Opk[qi][dp] = 0ull;

    for (int c = 0; c < NCH; c++) {
        __syncthreads();   // prev PV done reading Ps/Vs; smem writable
        // ---- store prefetched K chunk: Ktsd dup + Vs straight ----
        {
            *(float4*)(Vs + lm * 68 + lseg * 8)     = pf0;
            *(float4*)(Vs + lm * 68 + lseg * 8 + 4) = pf1;
            float v[8] = {pf0.x, pf0.y, pf0.z, pf0.w, pf1.x, pf1.y, pf1.z, pf1.w};
            #pragma unroll
            for (int j = 0; j < 8; j++)
                *(ull*)&Ktsd[(lseg * 8 + j) * 132 + 2 * lm] = pack2(v[j], v[j]);
        }
        // ---- prefetch next chunk (wraps harmlessly) ----
        {
            const int nc = (c + 1) & (NCH - 1);
            const float* gk = mem + (size_t)(nc * MC + lm) * HD + lseg * 8;
            pf0 = *(const float4*)gk;
            pf1 = *(const float4*)(gk + 4);
        }
        __syncthreads();

        // ---- S = Q @ Kc^T : pairs along q, K dup. 16 ffma2/d, no movs ----
        ull spk[4][4];
        #pragma unroll
        for (int qp = 0; qp < 4; qp++)
            #pragma unroll
            for (int mi = 0; mi < 4; mi++) spk[qp][mi] = 0ull;

        const float* qbase = Qts + qt * 8;
        const float* kbase = Ktsd + mt * 8;
        #pragma unroll 8
        for (int d = 0; d < HD; d++) {
            ulonglong2 qa = *(const ulonglong2*)(qbase + d * 260);      // q pairs 0,1
            ulonglong2 qb = *(const ulonglong2*)(qbase + d * 260 + 4);  // q pairs 2,3
            ulonglong2 ka = *(const ulonglong2*)(kbase + d * 132);      // m dup 0,1
            ulonglong2 kb = *(const ulonglong2*)(kbase + d * 132 + 4);  // m dup 2,3
            ffma2(spk[0][0], qa.x, ka.x); ffma2(spk[0][1], qa.x, ka.y);
            ffma2(spk[0][2], qa.x, kb.x); ffma2(spk[0][3], qa.x, kb.y);
            ffma2(spk[1][0], qa.y, ka.x); ffma2(spk[1][1], qa.y, ka.y);
            ffma2(spk[1][2], qa.y, kb.x); ffma2(spk[1][3], qa.y, kb.y);
            ffma2(spk[2][0], qb.x, ka.x); ffma2(spk[2][1], qb.x, ka.y);
            ffma2(spk[2][2], qb.x, kb.x); ffma2(spk[2][3], qb.x, kb.y);
            ffma2(spk[3][0], qb.y, ka.x); ffma2(spk[3][1], qb.y, ka.y);
            ffma2(spk[3][2], qb.y, kb.x); ffma2(spk[3][3], qb.y, kb.y);
        }

        // ---- online softmax (base 2) ----
        float s2[8][4];
        #pragma unroll
        for (int qp = 0; qp < 4; qp++)
            #pragma unroll
            for (int mi = 0; mi < 4; mi++)
                unpack2(spk[qp][mi], s2[2 * qp][mi], s2[2 * qp + 1][mi]);

        #pragma unroll
        for (int qi = 0; qi < 8; qi++) {
            float mx = fmaxf(fmaxf(s2[qi][0], s2[qi][1]),
                             fmaxf(s2[qi][2], s2[qi][3]));
            #pragma unroll
            for (int o = 8; o >= 1; o >>= 1)
                mx = fmaxf(mx, __shfl_xor_sync(0xffffffffu, mx, o));
            const int q = qt * 8 + qi;
            float mold = rMax[q];
            float mnew = fmaxf(mold, mx);
            float alpha = ex2(mold - mnew);
            float p0 = ex2(s2[qi][0] - mnew);
            float p1 = ex2(s2[qi][1] - mnew);
            float p2 = ex2(s2[qi][2] - mnew);
            float p3 = ex2(s2[qi][3] - mnew);
            float rs = (p0 + p1) + (p2 + p3);
            #pragma unroll
            for (int o = 8; o >= 1; o >>= 1)
                rs += __shfl_xor_sync(0xffffffffu, rs, o);
            if (mt == 0) {
                rMax[q]   = mnew;
                rLsum[q]  = rLsum[q] * alpha + rs;
                rAlpha[q] = alpha;
            }
            float4 pv = {p0, p1, p2, p3};
            *(float4*)(Ps + q * 68 + mt * 4) = pv;
        }
        __syncthreads();

        // ---- PV: O = O*alpha + P @ V over this group's 32 m rows ----
        {
            float a8[8];
            #pragma unroll
            for (int qi = 0; qi < 8; qi++) a8[qi] = rAlpha[qg + 32 * qi];
            #pragma unroll
            for (int qi = 0; qi < 8; qi++) {
                ull ap = pack2(a8[qi], a8[qi]);
                #pragma unroll
                for (int dp = 0; dp < 4; dp++) Opk[qi][dp] = mul2(Opk[qi][dp], ap);
            }
            const float* vbase = Vs + (g * 32) * 68 + dg * 8;
            const float* pbase = Ps + g * 32;
            #pragma unroll 4
            for (int mm = 0; mm < 32; mm++) {
                const float* vp = vbase + mm * 68;
                ulonglong2 v0 = *(const ulonglong2*)vp;       // d pairs 0,1
                ulonglong2 v1 = *(const ulonglong2*)(vp + 4); // d pairs 2,3
                #pragma unroll
                for (int qi = 0; qi < 8; qi++) {
                    float p = pbase[(qg + 32 * qi) * 68 + mm];
                    ull pd = pack2(p, p);
                    ffma2(Opk[qi][0], pd, v0.x);
                    ffma2(Opk[qi][1], pd, v0.y);
                    ffma2(Opk[qi][2], pd, v1.x);
                    ffma2(Opk[qi][3], pd, v1.y);
                }
            }
        }
    }

    // ---- combine the two m-group partials, normalize, store ----
    __syncthreads();
    if (g == 1) {
        #pragma unroll
        for (int qi = 0; qi < 8; qi++) {
            const int q = qg + 32 * qi;
            float4 o0, o1;
            unpack2(Opk[qi][0], o0.x, o0.y);
            unpack2(Opk[qi][1], o0.z, o0.w);
            unpack2(Opk[qi][2], o1.x, o1.y);
            unpack2(Opk[qi][3], o1.z, o1.w);
            *(float4*)(Ps + q * 68 + dg * 8)     = o0;
            *(float4*)(Ps + q * 68 + dg * 8 + 4) = o1;
        }
    }
    __syncthreads();
    if (g == 0) {
        #pragma unroll
        for (int qi = 0; qi < 8; qi++) {
            const int q = qg + 32 * qi;
            float inv = 1.0f / rLsum[q];
            float4 t0 = *(const float4*)(Ps + q * 68 + dg * 8);
            float4 t1 = *(const float4*)(Ps + q * 68 + dg * 8 + 4);
            float4 o0, o1;
            unpack2(Opk[qi][0], o0.x, o0.y);
            unpack2(Opk[qi][1], o0.z, o0.w);
            unpack2(Opk[qi][2], o1.x, o1.y);
            unpack2(Opk[qi][3], o1.z, o1.w);
            o0.x = (o0.x + t0.x) * inv; o0.y = (o0.y + t0.y) * inv;
            o0.z = (o0.z + t0.z) * inv; o0.w = (o0.w + t0.w) * inv;
            o1.x = (o1.x + t1.x) * inv; o1.y = (o1.y + t1.y) * inv;
            o1.z = (o1.z + t1.z) * inv; o1.w = (o1.w + t1.w) * inv;
            float* op = dst + (size_t)(r0 + q) * DIMSZ + h * HD + dg * 8;
            *(float4*)op       = o0;
            *(float4*)(op + 4) = o1;
        }
    }
}

// =======================================================================
extern "C" void kernel_launch(void* const* d_in, const int* in_sizes, int n_in,
                              void* d_out, int out_size)
{
    (void)in_sizes; (void)n_in; (void)out_size;
    const float* x    = (const float*)d_in[0];
    const float* mem  = (const float*)d_in[1];
    const float* Wq   = (const float*)d_in[2];
    const float* bq   = (const float*)d_in[3];
    const float* Wo   = (const float*)d_in[4];
    const float* bo   = (const float*)d_in[5];
    float* out = (float*)d_out;

    float *bufA = nullptr, *bufB = nullptr;
    cudaGetSymbolAddress((void**)&bufA, g_bufA);
    cudaGetSymbolAddress((void**)&bufB, g_bufB);

    cudaFuncSetAttribute(hopfield_attn_kernel,
                         cudaFuncAttributeMaxDynamicSharedMemorySize, SM_BYTES);

    dim3 gemm_grid(DIMSZ / 128, BL / 128);     // (8, 32)
    dim3 attn_grid(BL / QT, NHEADS);           // (16, 16)

    linear_kernel<<<gemm_grid, 256>>>(bufA, x, Wq, bq);
    hopfield_attn_kernel<<<attn_grid, 512, SM_BYTES>>>(bufB, bufA, mem);
    hopfield_attn_kernel<<<attn_grid, 512, SM_BYTES>>>(bufA, bufB, mem);
    linear_kernel<<<gemm_grid, 256>>>(out, bufA, Wo, bo);
}